// round 6
// baseline (speedup 1.0000x reference)
#include <cuda_runtime.h>
#include <cuda_fp16.h>
#include <cstdint>

// Problem constants: B=8, D=8, H=W=56, C=128, 4 heads x 32, windows (8,7,7),
// all pads zero. xy: 4096 windows x 49 tok; th/tw: 3584 x 56.
//
// fp16 storage, fp32 accumulate, mma.m16n8k16. Pair-permuted column layout:
// stored pos 4i..4i+3 = logical cols (2i,2i+1,2i+8,2i+9) -> A frags 2x LDS.64.
// B fragments (weights) are loaded DIRECTLY from pre-transposed fp16 weights
// in global memory (L1/L2 resident) -- no smem staging, no staging barriers.
// P register-resident (scores C-frag == PV A-frag). th/tw accumulate via REDG.

static constexpr int SH   = 144;  // stride (halves) for X/Q/K rows
static constexpr int VSH  = 80;   // stride for VT rows

static constexpr int OFF_X  = 0;                    // 64 x SH  (x, later attn out)
static constexpr int OFF_Q  = OFF_X + 64 * SH;
static constexpr int OFF_K  = OFF_Q + 64 * SH;
static constexpr int OFF_VT = OFF_K + 64 * SH;      // 128 x VSH (V^T: row=channel)
static constexpr int TOT_HALVES = OFF_VT + 128 * VSH;          // 37888
static constexpr int SMEM_BYTES = TOT_HALVES * 2 + 64 * 4;     // 76032 -> 2 CTAs/SM

// Pre-converted fp16 weights, transposed (row = output col n, col = k perm).
__device__ __align__(16) __half g_qkvwt[3][384 * 128];
__device__ __align__(16) __half g_projwt[3][128 * 128];

template <int BRANCH>
__device__ __forceinline__ int tok_index(int win, int tt) {
    if (BRANCH == 0) {                 // xy: (b, d, hb, wb) x (hh, ww)
        int b  = win >> 9;
        int d  = (win >> 6) & 7;
        int hb = (win >> 3) & 7;
        int wb = win & 7;
        int hh = tt / 7, wq = tt - hh * 7;
        return ((b * 8 + d) * 56 + hb * 7 + hh) * 56 + wb * 7 + wq;
    } else if (BRANCH == 1) {          // th: (b, hb, w) x (dd, hh)
        int b  = win / 448;
        int r  = win - b * 448;
        int hb = r / 56;
        int w  = r - hb * 56;
        int dd = tt / 7, hh = tt - dd * 7;
        return ((b * 8 + dd) * 56 + hb * 7 + hh) * 56 + w;
    } else {                           // tw: (b, h, wb) x (dd, ww)
        int b  = win / 448;
        int r  = win - b * 448;
        int h  = r >> 3;
        int wb = r & 7;
        int dd = tt / 7, wq = tt - dd * 7;
        return ((b * 8 + dd) * 56 + h) * 56 + wb * 7 + wq;
    }
}

// D += A(16x16) * B(16x8), f16 in, f32 accumulate.
__device__ __forceinline__ void mma16(float4& d, uint32_t a0, uint32_t a1,
                                      uint32_t a2, uint32_t a3,
                                      uint32_t b0, uint32_t b1) {
    asm volatile(
        "mma.sync.aligned.m16n8k16.row.col.f32.f16.f16.f32 "
        "{%0,%1,%2,%3}, {%4,%5,%6,%7}, {%8,%9}, {%0,%1,%2,%3};\n"
        : "+f"(d.x), "+f"(d.y), "+f"(d.z), "+f"(d.w)
        : "r"(a0), "r"(a1), "r"(a2), "r"(a3), "r"(b0), "r"(b1));
}

// Permuted position of logical column r16 within its 16-block.
__device__ __forceinline__ int vpos(int r) {
    int rb = r >> 4, r16 = r & 15;
    return rb * 16 + ((r16 & 7) >> 1) * 4 + (r16 & 1) + ((r16 & 8) ? 2 : 0);
}

__device__ __forceinline__ uint32_t h2u(float a, float b) {
    __half2 h = __floats2half2_rn(a, b);
    return *(uint32_t*)&h;
}

// ---------------- weight pre-conversion (runs once per launch) ----------------
__global__ void conv_weights(const float* __restrict__ w0, const float* __restrict__ w1,
                             const float* __restrict__ w2, const float* __restrict__ p0,
                             const float* __restrict__ p1, const float* __restrict__ p2) {
    int tid = blockIdx.x * 256 + threadIdx.x;
    const int QK = 3 * 384 * 128;
    if (tid < QK) {
        int br  = tid / (384 * 128);
        int rem = tid - br * 384 * 128;
        int n = rem >> 7, kp = rem & 127;
        int b = kp >> 4, p = kp & 15;
        int k = b * 16 + ((p >> 2) * 2) + (p & 1) + ((p & 2) ? 8 : 0);
        const float* src = (br == 0) ? w0 : (br == 1 ? w1 : w2);
        g_qkvwt[br][rem] = __float2half_rn(src[k * 384 + n]);
    } else {
        int t2  = tid - QK;
        int br  = t2 / (128 * 128);
        int rem = t2 - br * 16384;
        int n = rem >> 7, kp = rem & 127;
        int b = kp >> 4, p = kp & 15;
        int k = b * 16 + ((p >> 2) * 2) + (p & 1) + ((p & 2) ? 8 : 0);
        const float* src = (br == 0) ? p0 : (br == 1 ? p1 : p2);
        g_projwt[br][rem] = __float2half_rn(src[k * 128 + n]);
    }
}

// ---------------- fused window attention, one CTA per window ----------------
template <int BRANCH, int NTOK>
__global__ void __launch_bounds__(512, 2)
win_attn_h(const float* __restrict__ x,
           const float* __restrict__ qkvb, const float* __restrict__ projb,
           float* __restrict__ out)
{
    extern __shared__ __align__(16) __half smh[];
    int* tokidx = (int*)(smh + TOT_HALVES);

    const int t    = threadIdx.x;
    const int lane = t & 31;
    const int wrp  = t >> 5;        // 0..15
    const int g    = lane >> 2;
    const int tg   = lane & 3;
    const int win  = blockIdx.x;

    if (t < NTOK) tokidx[t] = tok_index<BRANCH>(win, t);

    // ---- x -> X (fp16, permuted), pad rows zeroed. 32 uint2 chunks/row ----
    for (int idx = t; idx < 64 * 32; idx += 512) {
        int r = idx >> 5, q = idx & 31;
        int b = q >> 2, i = q & 3;
        uint2 u = make_uint2(0u, 0u);
        if (r < NTOK) {
            const float* row = x + (size_t)tok_index<BRANCH>(win, r) * 128 + b * 16 + 2 * i;
            float2 lo = *(const float2*)row;        // cols 2i, 2i+1
            float2 hi = *(const float2*)(row + 8);  // cols 2i+8, 2i+9
            u.x = h2u(lo.x, lo.y);
            u.y = h2u(hi.x, hi.y);
        }
        *(uint2*)&smh[OFF_X + r * SH + q * 4] = u;
    }
    __syncthreads();

    const int mb = (wrp & 1) * 2;        // m-tiles {mb, mb+1}
    const int n0 = (wrp >> 1) * 16;      // n columns [n0, n0+16)
    const float qscale = 0.1767766952966369f;

    // ---- QKV GEMM: X(64x128) @ W chunk(128x128), chunks q,k,v ----
    // B frags straight from global (pre-transposed fp16, B-frag layout).
    // No cross-warp hazards inside this loop -> zero barriers until the end.
    #pragma unroll 1
    for (int cc = 0; cc < 3; cc++) {
        const __half* wsrc = g_qkvwt[BRANCH] + cc * 128 * 128;

        float4 acc[2][2];
        #pragma unroll
        for (int n = 0; n < 2; n++) {
            float b0 = qkvb[cc * 128 + n0 + n * 8 + 2 * tg];
            float b1 = qkvb[cc * 128 + n0 + n * 8 + 2 * tg + 1];
            acc[0][n] = make_float4(b0, b1, b0, b1);
            acc[1][n] = acc[0][n];
        }

        #pragma unroll 4
        for (int kt = 0; kt < 8; kt++) {
            int kb = kt * 16;
            uint2 A[2][2];
            #pragma unroll
            for (int m = 0; m < 2; m++) {
                int r = (mb + m) * 16 + g;
                A[m][0] = *(const uint2*)&smh[OFF_X + r * SH + kb + 4 * tg];
                A[m][1] = *(const uint2*)&smh[OFF_X + (r + 8) * SH + kb + 4 * tg];
            }
            uint2 B[2];
            #pragma unroll
            for (int n = 0; n < 2; n++) {
                int nn = n0 + n * 8 + g;
                B[n] = *(const uint2*)&wsrc[nn * 128 + kb + 4 * tg];
            }
            #pragma unroll
            for (int m = 0; m < 2; m++)
                #pragma unroll
                for (int n = 0; n < 2; n++)
                    mma16(acc[m][n], A[m][0].x, A[m][1].x, A[m][0].y, A[m][1].y,
                          B[n].x, B[n].y);
        }

        if (cc < 2) {   // q or k: activation layout, permuted half2 stores
            const int dst = (cc == 0) ? OFF_Q : OFF_K;
            const float mul = (cc == 0) ? qscale : 1.0f;
            #pragma unroll
            for (int m = 0; m < 2; m++) {
                int r = (mb + m) * 16 + g;
                #pragma unroll
                for (int n = 0; n < 2; n++) {
                    int pos = n0 + 4 * tg + 2 * n;   // perm of col n0+n*8+2tg
                    *(uint32_t*)&smh[dst + r * SH + pos] =
                        h2u(acc[m][n].x * mul, acc[m][n].y * mul);
                    *(uint32_t*)&smh[dst + (r + 8) * SH + pos] =
                        h2u(acc[m][n].z * mul, acc[m][n].w * mul);
                }
            }
        } else {        // v: transposed into VT[channel][token-perm]
            #pragma unroll
            for (int m = 0; m < 2; m++) {
                int r = (mb + m) * 16 + g, r2 = r + 8;
                #pragma unroll
                for (int n = 0; n < 2; n++) {
                    int c = n0 + n * 8 + 2 * tg;
                    smh[OFF_VT + c * VSH + vpos(r)]        = __float2half_rn(acc[m][n].x);
                    smh[OFF_VT + (c + 1) * VSH + vpos(r)]  = __float2half_rn(acc[m][n].y);
                    smh[OFF_VT + c * VSH + vpos(r2)]       = __float2half_rn(acc[m][n].z);
                    smh[OFF_VT + (c + 1) * VSH + vpos(r2)] = __float2half_rn(acc[m][n].w);
                }
            }
        }
    }
    __syncthreads();   // Q, K, VT all complete

    // ---- scores + softmax + P@V, P fully register-resident ----
    const int h  = wrp >> 2;
    const int mt = wrp & 3;
    const int r0 = mt * 16 + g;
    {
        float4 sacc[7];
        #pragma unroll
        for (int n = 0; n < 7; n++) sacc[n] = make_float4(0.f, 0.f, 0.f, 0.f);
        #pragma unroll
        for (int kt = 0; kt < 2; kt++) {
            int kb = h * 32 + kt * 16;
            uint2 A0 = *(const uint2*)&smh[OFF_Q + r0 * SH + kb + 4 * tg];
            uint2 A1 = *(const uint2*)&smh[OFF_Q + (r0 + 8) * SH + kb + 4 * tg];
            #pragma unroll
            for (int n = 0; n < 7; n++) {
                uint2 Bn = *(const uint2*)&smh[OFF_K + (n * 8 + g) * SH + kb + 4 * tg];
                mma16(sacc[n], A0.x, A1.x, A0.y, A1.y, Bn.x, Bn.y);
            }
        }

        // register softmax; rows r0 (x,y) and r0+8 (z,w) live in this lane quad
        if (NTOK < 56) {
            #pragma unroll
            for (int n = 0; n < 7; n++) {
                int j0 = 8 * n + 2 * tg;
                if (j0 >= NTOK)     { sacc[n].x = -1e30f; sacc[n].z = -1e30f; }
                if (j0 + 1 >= NTOK) { sacc[n].y = -1e30f; sacc[n].w = -1e30f; }
            }
        }
        float mA = -1e30f, mB = -1e30f;
        #pragma unroll
        for (int n = 0; n < 7; n++) {
            mA = fmaxf(mA, fmaxf(sacc[n].x, sacc[n].y));
            mB = fmaxf(mB, fmaxf(sacc[n].z, sacc[n].w));
        }
        #pragma unroll
        for (int o = 1; o <= 2; o <<= 1) {
            mA = fmaxf(mA, __shfl_xor_sync(~0u, mA, o));
            mB = fmaxf(mB, __shfl_xor_sync(~0u, mB, o));
        }
        float sA = 0.f, sB = 0.f;
        #pragma unroll
        for (int n = 0; n < 7; n++) {
            sacc[n].x = __expf(sacc[n].x - mA);
            sacc[n].y = __expf(sacc[n].y - mA);
            sacc[n].z = __expf(sacc[n].z - mB);
            sacc[n].w = __expf(sacc[n].w - mB);
            sA += sacc[n].x + sacc[n].y;
            sB += sacc[n].z + sacc[n].w;
        }
        #pragma unroll
        for (int o = 1; o <= 2; o <<= 1) {
            sA += __shfl_xor_sync(~0u, sA, o);
            sB += __shfl_xor_sync(~0u, sB, o);
        }
        float iA = 1.0f / sA, iB = 1.0f / sB;

        // Pack P into PV A-fragment registers (scores C-frag == A-frag layout).
        uint32_t pA[7], pB[7];
        #pragma unroll
        for (int n = 0; n < 7; n++) {
            pA[n] = h2u(sacc[n].x * iA, sacc[n].y * iA);
            pB[n] = h2u(sacc[n].z * iB, sacc[n].w * iB);
        }

        // ---- attn @ V -> X region (fp16, activation layout) ----
        float4 vacc[4];
        #pragma unroll
        for (int n = 0; n < 4; n++) vacc[n] = make_float4(0.f, 0.f, 0.f, 0.f);
        #pragma unroll
        for (int kt = 0; kt < 4; kt++) {
            int kb = kt * 16;
            uint32_t a0 = pA[2 * kt], a1 = pB[2 * kt];
            uint32_t a2 = (2 * kt + 1 < 7) ? pA[2 * kt + 1] : 0u;  // j pad = 0
            uint32_t a3 = (2 * kt + 1 < 7) ? pB[2 * kt + 1] : 0u;
            #pragma unroll
            for (int n = 0; n < 4; n++) {
                int c = h * 32 + n * 8 + g;
                uint2 Bn = *(const uint2*)&smh[OFF_VT + c * VSH + kb + 4 * tg];
                mma16(vacc[n], a0, a1, a2, a3, Bn.x, Bn.y);
            }
        }
        #pragma unroll
        for (int n = 0; n < 4; n++) {
            int pos = h * 32 + (n >> 1) * 16 + 4 * tg + 2 * (n & 1);
            *(uint32_t*)&smh[OFF_X + r0 * SH + pos]       = h2u(vacc[n].x, vacc[n].y);
            *(uint32_t*)&smh[OFF_X + (r0 + 8) * SH + pos] = h2u(vacc[n].z, vacc[n].w);
        }
    }
    __syncthreads();   // attn output complete

    // ---- proj GEMM: attnout(64x128) @ Wproj(128x128) -> global ----
    {
        const __half* psrc = g_projwt[BRANCH];
        float4 acc[2][2];
        #pragma unroll
        for (int n = 0; n < 2; n++) {
            float b0 = projb[n0 + n * 8 + 2 * tg];
            float b1 = projb[n0 + n * 8 + 2 * tg + 1];
            acc[0][n] = make_float4(b0, b1, b0, b1);
            acc[1][n] = acc[0][n];
        }
        #pragma unroll 4
        for (int kt = 0; kt < 8; kt++) {
            int kb = kt * 16;
            uint2 A[2][2];
            #pragma unroll
            for (int m = 0; m < 2; m++) {
                int r = (mb + m) * 16 + g;
                A[m][0] = *(const uint2*)&smh[OFF_X + r * SH + kb + 4 * tg];
                A[m][1] = *(const uint2*)&smh[OFF_X + (r + 8) * SH + kb + 4 * tg];
            }
            uint2 B[2];
            #pragma unroll
            for (int n = 0; n < 2; n++) {
                int nn = n0 + n * 8 + g;
                B[n] = *(const uint2*)&psrc[nn * 128 + kb + 4 * tg];
            }
            #pragma unroll
            for (int m = 0; m < 2; m++)
                #pragma unroll
                for (int n = 0; n < 2; n++)
                    mma16(acc[m][n], A[m][0].x, A[m][1].x, A[m][0].y, A[m][1].y,
                          B[n].x, B[n].y);
        }

        #pragma unroll
        for (int m = 0; m < 2; m++) {
            #pragma unroll
            for (int rr = 0; rr < 2; rr++) {
                int r = (mb + m) * 16 + g + rr * 8;
                if (r < NTOK) {
                    #pragma unroll
                    for (int n = 0; n < 2; n++) {
                        float2 val = rr ? make_float2(acc[m][n].z, acc[m][n].w)
                                        : make_float2(acc[m][n].x, acc[m][n].y);
                        size_t o = (size_t)tokidx[r] * 128 + n0 + n * 8 + 2 * tg;
                        if (BRANCH == 0) {
                            *(float2*)&out[o] = val;
                        } else {
                            // fire-and-forget accumulate (no read-return)
                            asm volatile("red.global.add.v2.f32 [%0], {%1, %2};"
                                         :: "l"(out + o), "f"(val.x), "f"(val.y)
                                         : "memory");
                        }
                    }
                }
            }
        }
    }
}

extern "C" void kernel_launch(void* const* d_in, const int* in_sizes, int n_in,
                              void* d_out, int out_size)
{
    const float* x         = (const float*)d_in[0];
    const float* qkv_w     = (const float*)d_in[1];
    const float* qkv_b     = (const float*)d_in[2];
    const float* qkv_th_w  = (const float*)d_in[3];
    const float* qkv_th_b  = (const float*)d_in[4];
    const float* qkv_tw_w  = (const float*)d_in[5];
    const float* qkv_tw_b  = (const float*)d_in[6];
    const float* proj_w    = (const float*)d_in[7];
    const float* proj_b    = (const float*)d_in[8];
    const float* proj_th_w = (const float*)d_in[9];
    const float* proj_th_b = (const float*)d_in[10];
    const float* proj_tw_w = (const float*)d_in[11];
    const float* proj_tw_b = (const float*)d_in[12];
    float* out = (float*)d_out;

    conv_weights<<<768, 256>>>(qkv_w, qkv_th_w, qkv_tw_w,
                               proj_w, proj_th_w, proj_tw_w);

    cudaFuncSetAttribute(win_attn_h<0, 49>,
                         cudaFuncAttributeMaxDynamicSharedMemorySize, SMEM_BYTES);
    cudaFuncSetAttribute(win_attn_h<1, 56>,
                         cudaFuncAttributeMaxDynamicSharedMemorySize, SMEM_BYTES);
    cudaFuncSetAttribute(win_attn_h<2, 56>,
                         cudaFuncAttributeMaxDynamicSharedMemorySize, SMEM_BYTES);

    // xy writes every output exactly once; th / tw accumulate via REDG.
    win_attn_h<0, 49><<<4096, 512, SMEM_BYTES>>>(x, qkv_b, proj_b, out);
    win_attn_h<1, 56><<<3584, 512, SMEM_BYTES>>>(x, qkv_th_b, proj_th_b, out);
    win_attn_h<2, 56><<<3584, 512, SMEM_BYTES>>>(x, qkv_tw_b, proj_tw_b, out);
}

// round 7
// speedup vs baseline: 1.0993x; 1.0993x over previous
#include <cuda_runtime.h>
#include <cuda_fp16.h>
#include <cstdint>

// Problem constants: B=8, D=8, H=W=56, C=128, 4 heads x 32, windows (8,7,7),
// all pads zero. xy: 4096 windows x 49 tok; th/tw: 3584 x 56.
//
// fp16 storage, fp32 accumulate, mma.m16n8k16.
// X/Q/K + weights: pair-permuted column layout (pos 4i..4i+3 = logical cols
// 2i,2i+1,2i+8,2i+9) -> A frags 2x LDS.64, B frags 1x LDS.64, staged in smem.
// V: plain row-major [token][channel]; PV B-frags via ldmatrix.x4.trans
// (replaces the 16-scalar-STS transpose scatter that dominated L1TEX).
// P register-resident (scores C-frag == PV A-frag). th/tw accumulate via REDG.

static constexpr int SH   = 144;  // stride (halves) for X/Q/K rows
static constexpr int WSH  = 144;  // stride for staged weight rows
static constexpr int VS   = 136;  // stride for V rows (272B -> conflict-free LDSM)

static constexpr int OFF_X  = 0;                    // 64 x SH (x, later attn out)
static constexpr int OFF_Q  = OFF_X + 64 * SH;
static constexpr int OFF_K  = OFF_Q + 64 * SH;
static constexpr int OFF_V  = OFF_K + 64 * SH;      // 64 x VS, plain layout
static constexpr int OFF_W  = OFF_V + 64 * VS;      // 128 x WSH staged weights
static constexpr int TOT_HALVES = OFF_W + 128 * WSH;           // 54784
static constexpr int SMEM_BYTES = TOT_HALVES * 2 + 64 * 4;     // 109824 -> 2 CTAs/SM

// Pre-converted fp16 weights, transposed (row = output col n, col = k perm).
__device__ __align__(16) __half g_qkvwt[3][384 * 128];
__device__ __align__(16) __half g_projwt[3][128 * 128];

template <int BRANCH>
__device__ __forceinline__ int tok_index(int win, int tt) {
    if (BRANCH == 0) {                 // xy: (b, d, hb, wb) x (hh, ww)
        int b  = win >> 9;
        int d  = (win >> 6) & 7;
        int hb = (win >> 3) & 7;
        int wb = win & 7;
        int hh = tt / 7, wq = tt - hh * 7;
        return ((b * 8 + d) * 56 + hb * 7 + hh) * 56 + wb * 7 + wq;
    } else if (BRANCH == 1) {          // th: (b, hb, w) x (dd, hh)
        int b  = win / 448;
        int r  = win - b * 448;
        int hb = r / 56;
        int w  = r - hb * 56;
        int dd = tt / 7, hh = tt - dd * 7;
        return ((b * 8 + dd) * 56 + hb * 7 + hh) * 56 + w;
    } else {                           // tw: (b, h, wb) x (dd, ww)
        int b  = win / 448;
        int r  = win - b * 448;
        int h  = r >> 3;
        int wb = r & 7;
        int dd = tt / 7, wq = tt - dd * 7;
        return ((b * 8 + dd) * 56 + h) * 56 + wb * 7 + wq;
    }
}

// D += A(16x16) * B(16x8), f16 in, f32 accumulate.
__device__ __forceinline__ void mma16(float4& d, uint32_t a0, uint32_t a1,
                                      uint32_t a2, uint32_t a3,
                                      uint32_t b0, uint32_t b1) {
    asm volatile(
        "mma.sync.aligned.m16n8k16.row.col.f32.f16.f16.f32 "
        "{%0,%1,%2,%3}, {%4,%5,%6,%7}, {%8,%9}, {%0,%1,%2,%3};\n"
        : "+f"(d.x), "+f"(d.y), "+f"(d.z), "+f"(d.w)
        : "r"(a0), "r"(a1), "r"(a2), "r"(a3), "r"(b0), "r"(b1));
}

// ldmatrix x4 with in-flight transpose (b16 elements).
__device__ __forceinline__ void ldsm_x4_t(uint32_t& r0, uint32_t& r1,
                                          uint32_t& r2, uint32_t& r3,
                                          uint32_t addr) {
    asm volatile("ldmatrix.sync.aligned.m8n8.x4.trans.shared.b16 "
                 "{%0,%1,%2,%3}, [%4];"
                 : "=r"(r0), "=r"(r1), "=r"(r2), "=r"(r3) : "r"(addr));
}

__device__ __forceinline__ uint32_t h2u(float a, float b) {
    __half2 h = __floats2half2_rn(a, b);
    return *(uint32_t*)&h;
}

// ---------------- weight pre-conversion (runs once per launch) ----------------
__global__ void conv_weights(const float* __restrict__ w0, const float* __restrict__ w1,
                             const float* __restrict__ w2, const float* __restrict__ p0,
                             const float* __restrict__ p1, const float* __restrict__ p2) {
    int tid = blockIdx.x * 256 + threadIdx.x;
    const int QK = 3 * 384 * 128;
    if (tid < QK) {
        int br  = tid / (384 * 128);
        int rem = tid - br * 384 * 128;
        int n = rem >> 7, kp = rem & 127;
        int b = kp >> 4, p = kp & 15;
        int k = b * 16 + ((p >> 2) * 2) + (p & 1) + ((p & 2) ? 8 : 0);
        const float* src = (br == 0) ? w0 : (br == 1 ? w1 : w2);
        g_qkvwt[br][rem] = __float2half_rn(src[k * 384 + n]);
    } else {
        int t2  = tid - QK;
        int br  = t2 / (128 * 128);
        int rem = t2 - br * 16384;
        int n = rem >> 7, kp = rem & 127;
        int b = kp >> 4, p = kp & 15;
        int k = b * 16 + ((p >> 2) * 2) + (p & 1) + ((p & 2) ? 8 : 0);
        const float* src = (br == 0) ? p0 : (br == 1 ? p1 : p2);
        g_projwt[br][rem] = __float2half_rn(src[k * 128 + n]);
    }
}

// ---------------- fused window attention, one CTA per window ----------------
template <int BRANCH, int NTOK>
__global__ void __launch_bounds__(512, 2)
win_attn_h(const float* __restrict__ x,
           const float* __restrict__ qkvb, const float* __restrict__ projb,
           float* __restrict__ out)
{
    extern __shared__ __align__(16) __half smh[];
    int* tokidx = (int*)(smh + TOT_HALVES);
    const uint32_t smem_u32 = (uint32_t)__cvta_generic_to_shared(smh);

    const int t    = threadIdx.x;
    const int lane = t & 31;
    const int wrp  = t >> 5;        // 0..15
    const int g    = lane >> 2;
    const int tg   = lane & 3;
    const int win  = blockIdx.x;

    if (t < NTOK) tokidx[t] = tok_index<BRANCH>(win, t);

    // ---- x -> X (fp16, permuted), pad rows zeroed. 32 uint2 chunks/row ----
    for (int idx = t; idx < 64 * 32; idx += 512) {
        int r = idx >> 5, q = idx & 31;
        int b = q >> 2, i = q & 3;
        uint2 u = make_uint2(0u, 0u);
        if (r < NTOK) {
            const float* row = x + (size_t)tok_index<BRANCH>(win, r) * 128 + b * 16 + 2 * i;
            float2 lo = *(const float2*)row;        // cols 2i, 2i+1
            float2 hi = *(const float2*)(row + 8);  // cols 2i+8, 2i+9
            u.x = h2u(lo.x, lo.y);
            u.y = h2u(hi.x, hi.y);
        }
        *(uint2*)&smh[OFF_X + r * SH + q * 4] = u;
    }
    __syncthreads();

    const int mb = (wrp & 1) * 2;        // m-tiles {mb, mb+1}
    const int n0 = (wrp >> 1) * 16;      // n columns [n0, n0+16)
    const float qscale = 0.1767766952966369f;

    // ---- QKV GEMM: X(64x128) @ W chunk(128x128), chunks q,k,v ----
    #pragma unroll 1
    for (int cc = 0; cc < 3; cc++) {
        const __half* wsrc = g_qkvwt[BRANCH] + cc * 128 * 128;
        for (int idx = t; idx < 128 * 16; idx += 512) {
            int rw = idx >> 4, c8 = idx & 15;
            *(uint4*)&smh[OFF_W + rw * WSH + c8 * 8] = *(const uint4*)&wsrc[rw * 128 + c8 * 8];
        }
        __syncthreads();

        float4 acc[2][2];
        #pragma unroll
        for (int n = 0; n < 2; n++) {
            float b0 = qkvb[cc * 128 + n0 + n * 8 + 2 * tg];
            float b1 = qkvb[cc * 128 + n0 + n * 8 + 2 * tg + 1];
            acc[0][n] = make_float4(b0, b1, b0, b1);
            acc[1][n] = acc[0][n];
        }

        #pragma unroll 4
        for (int kt = 0; kt < 8; kt++) {
            int kb = kt * 16;
            uint2 A[2][2];
            #pragma unroll
            for (int m = 0; m < 2; m++) {
                int r = (mb + m) * 16 + g;
                A[m][0] = *(const uint2*)&smh[OFF_X + r * SH + kb + 4 * tg];
                A[m][1] = *(const uint2*)&smh[OFF_X + (r + 8) * SH + kb + 4 * tg];
            }
            uint2 B[2];
            #pragma unroll
            for (int n = 0; n < 2; n++) {
                int nn = n0 + n * 8 + g;
                B[n] = *(const uint2*)&smh[OFF_W + nn * WSH + kb + 4 * tg];
            }
            #pragma unroll
            for (int m = 0; m < 2; m++)
                #pragma unroll
                for (int n = 0; n < 2; n++)
                    mma16(acc[m][n], A[m][0].x, A[m][1].x, A[m][0].y, A[m][1].y,
                          B[n].x, B[n].y);
        }

        if (cc < 2) {   // q or k: activation layout, permuted half2 stores
            const int dst = (cc == 0) ? OFF_Q : OFF_K;
            const float mul = (cc == 0) ? qscale : 1.0f;
            #pragma unroll
            for (int m = 0; m < 2; m++) {
                int r = (mb + m) * 16 + g;
                #pragma unroll
                for (int n = 0; n < 2; n++) {
                    int pos = n0 + 4 * tg + 2 * n;   // perm of col n0+n*8+2tg
                    *(uint32_t*)&smh[dst + r * SH + pos] =
                        h2u(acc[m][n].x * mul, acc[m][n].y * mul);
                    *(uint32_t*)&smh[dst + (r + 8) * SH + pos] =
                        h2u(acc[m][n].z * mul, acc[m][n].w * mul);
                }
            }
        } else {        // v: PLAIN row-major [token][channel], vector stores
            #pragma unroll
            for (int m = 0; m < 2; m++) {
                int r = (mb + m) * 16 + g;
                #pragma unroll
                for (int n = 0; n < 2; n++) {
                    int c = n0 + n * 8 + 2 * tg;
                    *(uint32_t*)&smh[OFF_V + r * VS + c] =
                        h2u(acc[m][n].x, acc[m][n].y);
                    *(uint32_t*)&smh[OFF_V + (r + 8) * VS + c] =
                        h2u(acc[m][n].z, acc[m][n].w);
                }
            }
        }
        __syncthreads();
    }

    // Prefetch proj weights into OFF_W (overlaps with scores/attn compute).
    {
        const __half* psrc = g_projwt[BRANCH];
        for (int idx = t; idx < 128 * 16; idx += 512) {
            int rw = idx >> 4, c8 = idx & 15;
            *(uint4*)&smh[OFF_W + rw * WSH + c8 * 8] = *(const uint4*)&psrc[rw * 128 + c8 * 8];
        }
    }

    // ---- scores + softmax + P@V, P fully register-resident ----
    const int h  = wrp >> 2;
    const int mt = wrp & 3;
    const int r0 = mt * 16 + g;
    {
        float4 sacc[7];
        #pragma unroll
        for (int n = 0; n < 7; n++) sacc[n] = make_float4(0.f, 0.f, 0.f, 0.f);
        #pragma unroll
        for (int kt = 0; kt < 2; kt++) {
            int kb = h * 32 + kt * 16;
            uint2 A0 = *(const uint2*)&smh[OFF_Q + r0 * SH + kb + 4 * tg];
            uint2 A1 = *(const uint2*)&smh[OFF_Q + (r0 + 8) * SH + kb + 4 * tg];
            #pragma unroll
            for (int n = 0; n < 7; n++) {
                uint2 Bn = *(const uint2*)&smh[OFF_K + (n * 8 + g) * SH + kb + 4 * tg];
                mma16(sacc[n], A0.x, A1.x, A0.y, A1.y, Bn.x, Bn.y);
            }
        }

        // register softmax; rows r0 (x,y) and r0+8 (z,w) live in this lane quad
        if (NTOK < 56) {
            #pragma unroll
            for (int n = 0; n < 7; n++) {
                int j0 = 8 * n + 2 * tg;
                if (j0 >= NTOK)     { sacc[n].x = -1e30f; sacc[n].z = -1e30f; }
                if (j0 + 1 >= NTOK) { sacc[n].y = -1e30f; sacc[n].w = -1e30f; }
            }
        }
        float mA = -1e30f, mB = -1e30f;
        #pragma unroll
        for (int n = 0; n < 7; n++) {
            mA = fmaxf(mA, fmaxf(sacc[n].x, sacc[n].y));
            mB = fmaxf(mB, fmaxf(sacc[n].z, sacc[n].w));
        }
        #pragma unroll
        for (int o = 1; o <= 2; o <<= 1) {
            mA = fmaxf(mA, __shfl_xor_sync(~0u, mA, o));
            mB = fmaxf(mB, __shfl_xor_sync(~0u, mB, o));
        }
        float sA = 0.f, sB = 0.f;
        #pragma unroll
        for (int n = 0; n < 7; n++) {
            sacc[n].x = __expf(sacc[n].x - mA);
            sacc[n].y = __expf(sacc[n].y - mA);
            sacc[n].z = __expf(sacc[n].z - mB);
            sacc[n].w = __expf(sacc[n].w - mB);
            sA += sacc[n].x + sacc[n].y;
            sB += sacc[n].z + sacc[n].w;
        }
        #pragma unroll
        for (int o = 1; o <= 2; o <<= 1) {
            sA += __shfl_xor_sync(~0u, sA, o);
            sB += __shfl_xor_sync(~0u, sB, o);
        }
        float iA = 1.0f / sA, iB = 1.0f / sB;

        // Pack P into PV A-fragment registers (scores C-frag == A-frag layout).
        uint32_t pA[7], pB[7];
        #pragma unroll
        for (int n = 0; n < 7; n++) {
            pA[n] = h2u(sacc[n].x * iA, sacc[n].y * iA);
            pB[n] = h2u(sacc[n].z * iB, sacc[n].w * iB);
        }

        // ---- attn @ V: B-frags via ldmatrix.trans on plain-layout V ----
        // Per x4.trans: lane groups address rows kb+li / kb+8+li at channel
        // c0 / c0+8 -> regs = {b0(n), b1(n), b0(n+1), b1(n+1)}.
        const int li  = lane & 7;
        const int grp = lane >> 3;
        float4 vacc[4];
        #pragma unroll
        for (int n = 0; n < 4; n++) vacc[n] = make_float4(0.f, 0.f, 0.f, 0.f);
        #pragma unroll
        for (int kt = 0; kt < 4; kt++) {
            int kb = kt * 16;
            int vrow = kb + ((grp & 1) << 3) + li;
            int vcol = h * 32 + ((grp >> 1) << 3);
            uint32_t addr = smem_u32 + (uint32_t)(OFF_V + vrow * VS + vcol) * 2;
            uint32_t b00, b01, b10, b11;   // n-pair 0: channels [h*32, h*32+16)
            ldsm_x4_t(b00, b01, b10, b11, addr);
            uint32_t b20, b21, b30, b31;   // n-pair 1: channels [h*32+16, h*32+32)
            ldsm_x4_t(b20, b21, b30, b31, addr + 32);

            uint32_t a0 = pA[2 * kt], a1 = pB[2 * kt];
            uint32_t a2 = (2 * kt + 1 < 7) ? pA[2 * kt + 1] : 0u;  // j pad = 0
            uint32_t a3 = (2 * kt + 1 < 7) ? pB[2 * kt + 1] : 0u;
            mma16(vacc[0], a0, a1, a2, a3, b00, b01);
            mma16(vacc[1], a0, a1, a2, a3, b10, b11);
            mma16(vacc[2], a0, a1, a2, a3, b20, b21);
            mma16(vacc[3], a0, a1, a2, a3, b30, b31);
        }
        #pragma unroll
        for (int n = 0; n < 4; n++) {
            int pos = h * 32 + (n >> 1) * 16 + 4 * tg + 2 * (n & 1);
            *(uint32_t*)&smh[OFF_X + r0 * SH + pos]       = h2u(vacc[n].x, vacc[n].y);
            *(uint32_t*)&smh[OFF_X + (r0 + 8) * SH + pos] = h2u(vacc[n].z, vacc[n].w);
        }
    }
    __syncthreads();   // attn output complete; proj weights staged

    // ---- proj GEMM: attnout(64x128) @ Wproj(128x128) -> global ----
    {
        float4 acc[2][2];
        #pragma unroll
        for (int n = 0; n < 2; n++) {
            float b0 = projb[n0 + n * 8 + 2 * tg];
            float b1 = projb[n0 + n * 8 + 2 * tg + 1];
            acc[0][n] = make_float4(b0, b1, b0, b1);
            acc[1][n] = acc[0][n];
        }
        #pragma unroll 4
        for (int kt = 0; kt < 8; kt++) {
            int kb = kt * 16;
            uint2 A[2][2];
            #pragma unroll
            for (int m = 0; m < 2; m++) {
                int r = (mb + m) * 16 + g;
                A[m][0] = *(const uint2*)&smh[OFF_X + r * SH + kb + 4 * tg];
                A[m][1] = *(const uint2*)&smh[OFF_X + (r + 8) * SH + kb + 4 * tg];
            }
            uint2 B[2];
            #pragma unroll
            for (int n = 0; n < 2; n++) {
                int nn = n0 + n * 8 + g;
                B[n] = *(const uint2*)&smh[OFF_W + nn * WSH + kb + 4 * tg];
            }
            #pragma unroll
            for (int m = 0; m < 2; m++)
                #pragma unroll
                for (int n = 0; n < 2; n++)
                    mma16(acc[m][n], A[m][0].x, A[m][1].x, A[m][0].y, A[m][1].y,
                          B[n].x, B[n].y);
        }

        #pragma unroll
        for (int m = 0; m < 2; m++) {
            #pragma unroll
            for (int rr = 0; rr < 2; rr++) {
                int r = (mb + m) * 16 + g + rr * 8;
                if (r < NTOK) {
                    #pragma unroll
                    for (int n = 0; n < 2; n++) {
                        float2 val = rr ? make_float2(acc[m][n].z, acc[m][n].w)
                                        : make_float2(acc[m][n].x, acc[m][n].y);
                        size_t o = (size_t)tokidx[r] * 128 + n0 + n * 8 + 2 * tg;
                        if (BRANCH == 0) {
                            *(float2*)&out[o] = val;
                        } else {
                            asm volatile("red.global.add.v2.f32 [%0], {%1, %2};"
                                         :: "l"(out + o), "f"(val.x), "f"(val.y)
                                         : "memory");
                        }
                    }
                }
            }
        }
    }
}

extern "C" void kernel_launch(void* const* d_in, const int* in_sizes, int n_in,
                              void* d_out, int out_size)
{
    const float* x         = (const float*)d_in[0];
    const float* qkv_w     = (const float*)d_in[1];
    const float* qkv_b     = (const float*)d_in[2];
    const float* qkv_th_w  = (const float*)d_in[3];
    const float* qkv_th_b  = (const float*)d_in[4];
    const float* qkv_tw_w  = (const float*)d_in[5];
    const float* qkv_tw_b  = (const float*)d_in[6];
    const float* proj_w    = (const float*)d_in[7];
    const float* proj_b    = (const float*)d_in[8];
    const float* proj_th_w = (const float*)d_in[9];
    const float* proj_th_b = (const float*)d_in[10];
    const float* proj_tw_w = (const float*)d_in[11];
    const float* proj_tw_b = (const float*)d_in[12];
    float* out = (float*)d_out;

    conv_weights<<<768, 256>>>(qkv_w, qkv_th_w, qkv_tw_w,
                               proj_w, proj_th_w, proj_tw_w);

    cudaFuncSetAttribute(win_attn_h<0, 49>,
                         cudaFuncAttributeMaxDynamicSharedMemorySize, SMEM_BYTES);
    cudaFuncSetAttribute(win_attn_h<1, 56>,
                         cudaFuncAttributeMaxDynamicSharedMemorySize, SMEM_BYTES);
    cudaFuncSetAttribute(win_attn_h<2, 56>,
                         cudaFuncAttributeMaxDynamicSharedMemorySize, SMEM_BYTES);

    // xy writes every output exactly once; th / tw accumulate via REDG.
    win_attn_h<0, 49><<<4096, 512, SMEM_BYTES>>>(x, qkv_b, proj_b, out);
    win_attn_h<1, 56><<<3584, 512, SMEM_BYTES>>>(x, qkv_th_b, proj_th_b, out);
    win_attn_h<2, 56><<<3584, 512, SMEM_BYTES>>>(x, qkv_tw_b, proj_tw_b, out);
}